// round 4
// baseline (speedup 1.0000x reference)
#include <cuda_runtime.h>
#include <cstdint>

// Fused GRU cell — 3xTF32 precision-emulated mma.sync version.
//   z = sigmoid(x@Wz + h@Uz + bz)
//   r = sigmoid(x@Wr + h@Ur + br)
//   hh = tanh(x@Wh + (r*h)@Uh + bh)
//   out = z*h + (1-z)*hh
//
// Each operand split in registers: v = hi(tf32) + lo(tf32), product computed
// as lo*hi + hi*lo + hi*hi (3 MMAs) -> fp32-level accuracy on tensor cores.
//
// CTA: 64 rows (M), full 256 cols processed as 2 slabs of 128.
// Phase 1: Gr over stacked K=512 ([x|h] @ [Wr;Ur]) -> r*h into smem.
// Phase 2: Gz ([x|h]@[Wz;Uz]) and Gh ([x|rh]@[Wh;Uh]) together -> fused epilogue.
// Weights streamed via cp.async, double buffered, 8-deep K chunks.

#define HID   256
#define MT    64
#define NSLAB 128
#define XSTR  260      // x/h/rh smem row stride (floats): conflict-free A frags
#define WSTR  136      // weight smem row stride: conflict-free B frags
#define NCHUNK 64      // 512 stacked K / 8

__device__ __forceinline__ unsigned sm32(const void* p) {
    return (unsigned)__cvta_generic_to_shared(p);
}
__device__ __forceinline__ void cp16(void* s, const void* g) {
    asm volatile("cp.async.cg.shared.global [%0], [%1], 16;\n" :: "r"(sm32(s)), "l"(g));
}
__device__ __forceinline__ void cp_commit() { asm volatile("cp.async.commit_group;\n"); }
__device__ __forceinline__ void cp_wait0()  { asm volatile("cp.async.wait_group 0;\n" ::: "memory"); }

__device__ __forceinline__ unsigned tf32_rna(float v) {
    unsigned r;
    asm volatile("cvt.rna.tf32.f32 %0, %1;\n" : "=r"(r) : "f"(v));
    return r;
}
// split v into hi + lo tf32 parts (hi+lo ~ 22-bit accurate)
__device__ __forceinline__ void tf32_split(float v, unsigned& hi, unsigned& lo) {
    hi = tf32_rna(v);
    float r = v - __uint_as_float(hi);   // tf32 values are exact fp32
    lo = tf32_rna(r);
}

__device__ __forceinline__ void mma8(float c[4], const unsigned a[4], const unsigned b[2]) {
    asm volatile(
        "mma.sync.aligned.m16n8k8.row.col.f32.tf32.tf32.f32 "
        "{%0,%1,%2,%3}, {%4,%5,%6,%7}, {%8,%9}, {%0,%1,%2,%3};\n"
        : "+f"(c[0]), "+f"(c[1]), "+f"(c[2]), "+f"(c[3])
        : "r"(a[0]), "r"(a[1]), "r"(a[2]), "r"(a[3]), "r"(b[0]), "r"(b[1]));
}
// 3xTF32: c += a*b with split operands (drop lo*lo, ~2^-22 per term)
__device__ __forceinline__ void mma3(float c[4],
                                     const unsigned ahi[4], const unsigned alo[4],
                                     const unsigned bhi[2], const unsigned blo[2]) {
    mma8(c, alo, bhi);
    mma8(c, ahi, blo);
    mma8(c, ahi, bhi);
}

__device__ __forceinline__ float sigmoidf_(float v) { return 1.0f / (1.0f + __expf(-v)); }

__global__ void __launch_bounds__(256, 1)
gru_fused_tf32x3(const float* __restrict__ x,  const float* __restrict__ h,
                 const float* __restrict__ Wz, const float* __restrict__ Uz, const float* __restrict__ bz,
                 const float* __restrict__ Wr, const float* __restrict__ Ur, const float* __restrict__ br,
                 const float* __restrict__ Wh, const float* __restrict__ Uh, const float* __restrict__ bh,
                 float* __restrict__ out, float* __restrict__ out2, int rows)
{
    extern __shared__ float smem[];
    float* xs  = smem;                 // 64 x 260
    float* hs  = xs  + MT * XSTR;      // 64 x 260
    float* rhs = hs  + MT * XSTR;      // 64 x 260  (r*h)
    float* wA  = rhs + MT * XSTR;      // 2 x 8 x 136
    float* wB  = wA  + 2 * 8 * WSTR;   // 2 x 8 x 136

    const int tid  = threadIdx.x;
    const int lane = tid & 31;
    const int warp = tid >> 5;
    const int tg   = lane >> 2;   // group id (0..7)
    const int tq   = lane & 3;    // thread-in-group (0..3)
    const int m0   = (warp >> 2) * 32;  // warp M origin (0 or 32)
    const int n0w  = (warp & 3) * 32;   // warp N origin within slab (0..96)

    const int row0 = blockIdx.x * MT;

    // ---- load x / h tiles (full fp32 in smem; split happens at frag load) ----
    for (int i = tid; i < MT * 64; i += 256) {
        int r  = i >> 6;
        int c4 = (i & 63) << 2;
        int gr = row0 + r;
        float4 vx = make_float4(0.f, 0.f, 0.f, 0.f), vh = vx;
        if (gr < rows) {
            vx = *(const float4*)(x + (size_t)gr * HID + c4);
            vh = *(const float4*)(h + (size_t)gr * HID + c4);
        }
        *(float4*)(xs + r * XSTR + c4) = vx;
        *(float4*)(hs + r * XSTR + c4) = vh;
    }

    const int pr = tid >> 5;          // chunk row 0..7
    const int pc = (tid & 31) << 2;   // chunk col*4 (0..124)

    // prefetch one 8x128 weight chunk of the stacked matrix [W;U] (K=512)
    auto pfw = [&](const float* W, const float* U, int kc, int slab, float* dst) {
        int k = kc * 8 + pr;
        const float* src = (k < HID) ? (W + (size_t)k * HID) : (U + (size_t)(k - HID) * HID);
        cp16(dst + pr * WSTR + pc, src + slab * NSLAB + pc);
    };

    auto load_a = [&](unsigned ahi[2][4], unsigned alo[2][4], const float* S, int kl) {
        #pragma unroll
        for (int mt = 0; mt < 2; ++mt) {
            const float* p = S + (m0 + mt * 16 + tg) * XSTR + kl + tq;
            tf32_split(p[0],            ahi[mt][0], alo[mt][0]);
            tf32_split(p[8 * XSTR],     ahi[mt][1], alo[mt][1]);
            tf32_split(p[4],            ahi[mt][2], alo[mt][2]);
            tf32_split(p[8 * XSTR + 4], ahi[mt][3], alo[mt][3]);
        }
    };
    auto load_b = [&](unsigned bhi[4][2], unsigned blo[4][2], const float* wbuf) {
        #pragma unroll
        for (int nt = 0; nt < 4; ++nt) {
            const float* p = wbuf + tq * WSTR + n0w + nt * 8 + tg;
            tf32_split(p[0],        bhi[nt][0], blo[nt][0]);
            tf32_split(p[4 * WSTR], bhi[nt][1], blo[nt][1]);
        }
    };

    // ================= Phase 1: r = sigmoid(x@Wr + h@Ur + br); rhs = r*h =================
    for (int s = 0; s < 2; ++s) {
        float cr[2][4][4];
        #pragma unroll
        for (int i = 0; i < 2; ++i)
            #pragma unroll
            for (int j = 0; j < 4; ++j)
                #pragma unroll
                for (int k = 0; k < 4; ++k) cr[i][j][k] = 0.f;

        pfw(Wr, Ur, 0, s, wA);
        cp_commit();
        for (int kc = 0; kc < NCHUNK; ++kc) {
            cp_wait0();
            __syncthreads();
            if (kc + 1 < NCHUNK) {
                pfw(Wr, Ur, kc + 1, s, wA + ((kc + 1) & 1) * (8 * WSTR));
                cp_commit();
            }
            const float* S = (kc < 32) ? xs : hs;
            int kl = (kc & 31) * 8;
            unsigned ahi[2][4], alo[2][4], bhi[4][2], blo[4][2];
            load_a(ahi, alo, S, kl);
            load_b(bhi, blo, wA + (kc & 1) * (8 * WSTR));
            #pragma unroll
            for (int mt = 0; mt < 2; ++mt)
                #pragma unroll
                for (int nt = 0; nt < 4; ++nt)
                    mma3(cr[mt][nt], ahi[mt], alo[mt], bhi[nt], blo[nt]);
        }
        __syncthreads();
        // epilogue: rhs = sigmoid(Gr + br) * h
        #pragma unroll
        for (int nt = 0; nt < 4; ++nt) {
            int colg = s * NSLAB + n0w + nt * 8 + 2 * tq;
            float b0 = __ldg(br + colg), b1 = __ldg(br + colg + 1);
            #pragma unroll
            for (int mt = 0; mt < 2; ++mt) {
                int r0 = m0 + mt * 16 + tg;
                int r1 = r0 + 8;
                float rr;
                rr = sigmoidf_(cr[mt][nt][0] + b0); rhs[r0 * XSTR + colg    ] = rr * hs[r0 * XSTR + colg    ];
                rr = sigmoidf_(cr[mt][nt][1] + b1); rhs[r0 * XSTR + colg + 1] = rr * hs[r0 * XSTR + colg + 1];
                rr = sigmoidf_(cr[mt][nt][2] + b0); rhs[r1 * XSTR + colg    ] = rr * hs[r1 * XSTR + colg    ];
                rr = sigmoidf_(cr[mt][nt][3] + b1); rhs[r1 * XSTR + colg + 1] = rr * hs[r1 * XSTR + colg + 1];
            }
        }
        __syncthreads();
    }

    // ================= Phase 2: Gz and Gh together, fused epilogue =================
    for (int s = 0; s < 2; ++s) {
        float cz[2][4][4], ct[2][4][4];
        #pragma unroll
        for (int i = 0; i < 2; ++i)
            #pragma unroll
            for (int j = 0; j < 4; ++j)
                #pragma unroll
                for (int k = 0; k < 4; ++k) { cz[i][j][k] = 0.f; ct[i][j][k] = 0.f; }

        pfw(Wz, Uz, 0, s, wA);
        pfw(Wh, Uh, 0, s, wB);
        cp_commit();
        for (int kc = 0; kc < NCHUNK; ++kc) {
            cp_wait0();
            __syncthreads();
            if (kc + 1 < NCHUNK) {
                pfw(Wz, Uz, kc + 1, s, wA + ((kc + 1) & 1) * (8 * WSTR));
                pfw(Wh, Uh, kc + 1, s, wB + ((kc + 1) & 1) * (8 * WSTR));
                cp_commit();
            }
            int kl = (kc & 31) * 8;
            unsigned aZhi[2][4], aZlo[2][4], aHhi[2][4], aHlo[2][4];
            unsigned bZhi[4][2], bZlo[4][2], bHhi[4][2], bHlo[4][2];
            if (kc < 32) { load_a(aZhi, aZlo, xs, kl); load_a(aHhi, aHlo, xs, kl); }
            else         { load_a(aZhi, aZlo, hs, kl); load_a(aHhi, aHlo, rhs, kl); }
            load_b(bZhi, bZlo, wA + (kc & 1) * (8 * WSTR));
            load_b(bHhi, bHlo, wB + (kc & 1) * (8 * WSTR));
            #pragma unroll
            for (int mt = 0; mt < 2; ++mt)
                #pragma unroll
                for (int nt = 0; nt < 4; ++nt) {
                    mma3(cz[mt][nt], aZhi[mt], aZlo[mt], bZhi[nt], bZlo[nt]);
                    mma3(ct[mt][nt], aHhi[mt], aHlo[mt], bHhi[nt], bHlo[nt]);
                }
        }
        __syncthreads();
        // epilogue: out = z*h + (1-z)*tanh(Gh + bh)
        #pragma unroll
        for (int nt = 0; nt < 4; ++nt) {
            int colg = s * NSLAB + n0w + nt * 8 + 2 * tq;
            float bz0 = __ldg(bz + colg), bz1 = __ldg(bz + colg + 1);
            float bh0 = __ldg(bh + colg), bh1 = __ldg(bh + colg + 1);
            #pragma unroll
            for (int mt = 0; mt < 2; ++mt) {
                int r0 = m0 + mt * 16 + tg;
                int r1 = r0 + 8;
                {
                    float z0 = sigmoidf_(cz[mt][nt][0] + bz0);
                    float z1 = sigmoidf_(cz[mt][nt][1] + bz1);
                    float t0 = tanhf(ct[mt][nt][0] + bh0);
                    float t1 = tanhf(ct[mt][nt][1] + bh1);
                    float hv0 = hs[r0 * XSTR + colg];
                    float hv1 = hs[r0 * XSTR + colg + 1];
                    float o0 = z0 * hv0 + (1.f - z0) * t0;
                    float o1 = z1 * hv1 + (1.f - z1) * t1;
                    int gr = row0 + r0;
                    if (gr < rows) {
                        *(float2*)(out + (size_t)gr * HID + colg) = make_float2(o0, o1);
                        if (out2) *(float2*)(out2 + (size_t)gr * HID + colg) = make_float2(o0, o1);
                    }
                }
                {
                    float z0 = sigmoidf_(cz[mt][nt][2] + bz0);
                    float z1 = sigmoidf_(cz[mt][nt][3] + bz1);
                    float t0 = tanhf(ct[mt][nt][2] + bh0);
                    float t1 = tanhf(ct[mt][nt][3] + bh1);
                    float hv0 = hs[r1 * XSTR + colg];
                    float hv1 = hs[r1 * XSTR + colg + 1];
                    float o0 = z0 * hv0 + (1.f - z0) * t0;
                    float o1 = z1 * hv1 + (1.f - z1) * t1;
                    int gr = row0 + r1;
                    if (gr < rows) {
                        *(float2*)(out + (size_t)gr * HID + colg) = make_float2(o0, o1);
                        if (out2) *(float2*)(out2 + (size_t)gr * HID + colg) = make_float2(o0, o1);
                    }
                }
            }
        }
        __syncthreads();
    }
}

extern "C" void kernel_launch(void* const* d_in, const int* in_sizes, int n_in,
                              void* d_out, int out_size) {
    const float* x  = (const float*)d_in[0];
    const float* h  = (const float*)d_in[1];
    const float* Wz = (const float*)d_in[2];
    const float* Uz = (const float*)d_in[3];
    const float* bz = (const float*)d_in[4];
    const float* Wr = (const float*)d_in[5];
    const float* Ur = (const float*)d_in[6];
    const float* br = (const float*)d_in[7];
    const float* Wh = (const float*)d_in[8];
    const float* Uh = (const float*)d_in[9];
    const float* bh = (const float*)d_in[10];
    (void)n_in;

    int rows = in_sizes[0] / HID;
    float* out = (float*)d_out;
    float* out2 = ((long long)out_size >= 2LL * rows * HID) ? out + (size_t)rows * HID : nullptr;

    const int smem_bytes = (3 * MT * XSTR + 2 * 2 * 8 * WSTR) * (int)sizeof(float); // 217088
    cudaFuncSetAttribute(gru_fused_tf32x3, cudaFuncAttributeMaxDynamicSharedMemorySize, smem_bytes);

    int grid = (rows + MT - 1) / MT;
    gru_fused_tf32x3<<<grid, 256, smem_bytes>>>(x, h, Wz, Uz, bz, Wr, Ur, br, Wh, Uh, bh,
                                                out, out2, rows);
}